// round 2
// baseline (speedup 1.0000x reference)
#include <cuda_runtime.h>

#define BATCH 32768
#define HID   128
#define PRE   12

// ---------------- device scratch ------------------------------------------------
__device__ float  g_W[4 * HID * HID];                 // combined W_ih + W_hh  [512][128]
__device__ float  g_bz[4 * HID];                      // combined bias
__device__ float  g_H[(size_t)BATCH * PRE * HID];     // hidden states, layout (B, PRE, HID)
__device__ float  g_c[(size_t)BATCH * HID];           // cell state (in-place per step)
__device__ float  g_X[(size_t)BATCH * PRE * 50];      // Linear1 output, layout (B*PRE, 50)
__device__ double g_part1[512 * 2];                   // BN1 partials (accumulated over 12 steps)
__device__ double g_part2[3072 * 2];                  // BN2 partials
__device__ double g_part3[1024 * 2];                  // BN3 partials
__device__ float  g_s1[64];                           // [0]=alpha1, [1..50]=bias_eff1
__device__ float  g_s2[4];                            // [0]=alpha2, [1]=beta2-alpha2*m2
__device__ float  g_s3[104];                          // [0..99]=alpha3*W2, [100..101]=b2_eff

__device__ __forceinline__ float sigf(float x) {
    return 1.0f / (1.0f + __expf(-x));
}
__device__ __forceinline__ float tanhfast(float x) {
    return fmaf(2.0f, 1.0f / (1.0f + __expf(-2.0f * x)), -1.0f);
}
__device__ __forceinline__ void dot4(float& a, const float4& u, const float4& v) {
    a = fmaf(u.x, v.x, fmaf(u.y, v.y, fmaf(u.z, v.z, fmaf(u.w, v.w, a))));
}

// ---------------- prep: combine weights/biases, zero BN1 partials ---------------
__global__ void k_prep(const float* __restrict__ Wih, const float* __restrict__ Whh,
                       const float* __restrict__ bih, const float* __restrict__ bhh) {
    int i = blockIdx.x * blockDim.x + threadIdx.x;
    for (int idx = i; idx < 4 * HID * HID; idx += gridDim.x * blockDim.x)
        g_W[idx] = Wih[idx] + Whh[idx];
    if (i < 4 * HID) g_bz[i] = bih[i] + bhh[i];
    if (i < 1024)    g_part1[i] = 0.0;
}

// ---------------- one LSTM step -------------------------------------------------
// Block: 256 threads, 64 batch rows. W streamed via SMEM in 4 chunks of 32 k-cols
// (all 4 gate rows per k), so each thread holds i/f/g/o accumulators for its
// (row,k) pairs and does the elementwise update locally.
__global__ __launch_bounds__(256) void k_step(int t, const float* __restrict__ h0_in,
                                              const float* __restrict__ c0_in) {
    extern __shared__ float smem[];
    float* h_s = smem;             // 64 x 132 (padded)
    float* Wb  = smem + 64 * 132;  // 128 x 132 (4 gates x 32 k-rows)

    const int tid = threadIdx.x;
    const int rq  = tid >> 4;      // 0..15 -> 4 rows each
    const int kq  = tid & 15;      // 0..15 -> 2 k each
    const int r0  = blockIdx.x * 64;

    const float* hsrc;
    int hstride;
    if (t == 0) { hsrc = h0_in + (size_t)r0 * HID;                 hstride = HID; }
    else        { hsrc = g_H + ((size_t)r0 * PRE + (t - 1)) * HID; hstride = PRE * HID; }

    for (int idx = tid; idx < 64 * 32; idx += 256) {
        int row = idx >> 5, c4 = (idx & 31) << 2;
        float4 v = *(const float4*)(hsrc + (size_t)row * hstride + c4);
        *(float4*)(h_s + row * 132 + c4) = v;
    }

    const float* csrc = (t == 0) ? (c0_in + (size_t)r0 * HID) : (g_c + (size_t)r0 * HID);
    float*       cdst = g_c + (size_t)r0 * HID;

    double lsum = 0.0, lsq = 0.0;
    const int kl = kq * 2;

    for (int kc = 0; kc < 4; ++kc) {
        __syncthreads();  // protect Wb from previous chunk's readers / h_s load
        for (int idx = tid; idx < 128 * 32; idx += 256) {
            int row = idx >> 5, c4 = (idx & 31) << 2;
            int g = row >> 5, kk = row & 31;
            float4 v = *(const float4*)(g_W + (g * HID + kc * 32 + kk) * HID + c4);
            *(float4*)(Wb + row * 132 + c4) = v;
        }
        __syncthreads();

        const int kglob = kc * 32 + kl;
        float acc[4][4][2];
#pragma unroll
        for (int g = 0; g < 4; ++g) {
            float b0 = g_bz[g * HID + kglob];
            float b1 = g_bz[g * HID + kglob + 1];
#pragma unroll
            for (int i = 0; i < 4; ++i) { acc[g][i][0] = b0; acc[g][i][1] = b1; }
        }

        const float* hrow = h_s + (rq * 4) * 132;
        const float* wrow = Wb + kl * 132;
#pragma unroll 4
        for (int m4 = 0; m4 < 32; ++m4) {
            const int mo = m4 * 4;
            float4 hv[4];
#pragma unroll
            for (int i = 0; i < 4; ++i)
                hv[i] = *(const float4*)(hrow + i * 132 + mo);
#pragma unroll
            for (int g = 0; g < 4; ++g) {
                const float* wp = wrow + g * 32 * 132 + mo;
                float4 w0 = *(const float4*)(wp);
                float4 w1 = *(const float4*)(wp + 132);
#pragma unroll
                for (int i = 0; i < 4; ++i) {
                    dot4(acc[g][i][0], hv[i], w0);
                    dot4(acc[g][i][1], hv[i], w1);
                }
            }
        }

        // elementwise gate update for this k-chunk
#pragma unroll
        for (int i = 0; i < 4; ++i) {
            int lrow = rq * 4 + i;
            int b    = r0 + lrow;
            float2 cv = *(const float2*)(csrc + (size_t)lrow * HID + kglob);
            float2 nc, nh;
#pragma unroll
            for (int kk = 0; kk < 2; ++kk) {
                float zi = acc[0][i][kk], zf = acc[1][i][kk];
                float zg = acc[2][i][kk], zo = acc[3][i][kk];
                float ig = sigf(zi), fg = sigf(zf), gg = tanhfast(zg), og = sigf(zo);
                float cold = kk ? cv.y : cv.x;
                float c2 = fmaf(fg, cold, ig * gg);
                float h2 = og * tanhfast(c2);
                if (kk == 0) { nc.x = c2; nh.x = h2; }
                else         { nc.y = c2; nh.y = h2; }
                lsum += h2;
                lsq  += (double)h2 * (double)h2;
            }
            *(float2*)(cdst + (size_t)lrow * HID + kglob)         = nc;
            *(float2*)(g_H + ((size_t)b * PRE + t) * HID + kglob) = nh;
        }
    }

    // deterministic block reduction, then single-writer accumulate
    __shared__ double rsum[8], rsq[8];
#pragma unroll
    for (int o = 16; o; o >>= 1) {
        lsum += __shfl_down_sync(0xffffffffu, lsum, o);
        lsq  += __shfl_down_sync(0xffffffffu, lsq, o);
    }
    if ((tid & 31) == 0) { rsum[tid >> 5] = lsum; rsq[tid >> 5] = lsq; }
    __syncthreads();
    if (tid == 0) {
        double a = 0, b = 0;
        for (int w = 0; w < 8; ++w) { a += rsum[w]; b += rsq[w]; }
        g_part1[blockIdx.x * 2]     += a;   // sole writer, sequential launches -> deterministic
        g_part1[blockIdx.x * 2 + 1] += b;
    }
}

// ---------------- finalize BN1, fold into Linear1 bias --------------------------
__global__ void k_fin1(const float* __restrict__ gamma1, const float* __restrict__ beta1,
                       const float* __restrict__ W1, const float* __restrict__ b1) {
    __shared__ double s0[256], s1b[256];
    __shared__ float sa, sd;
    int tid = threadIdx.x;
    s0[tid]  = g_part1[tid * 2]     + g_part1[(tid + 256) * 2];
    s1b[tid] = g_part1[tid * 2 + 1] + g_part1[(tid + 256) * 2 + 1];
    __syncthreads();
    for (int o = 128; o; o >>= 1) {
        if (tid < o) { s0[tid] += s0[tid + o]; s1b[tid] += s1b[tid + o]; }
        __syncthreads();
    }
    if (tid == 0) {
        double N = (double)BATCH * PRE * HID;
        double m = s0[0] / N;
        double v = s1b[0] / N - m * m;
        double a = (double)gamma1[0] / sqrt(v + 1e-5);
        sa = (float)a;
        sd = (float)((double)beta1[0] - a * m);
        g_s1[0] = sa;
    }
    __syncthreads();
    if (tid < 50) {
        float rs = 0.0f;
        for (int k = 0; k < HID; ++k) rs += W1[tid * HID + k];
        g_s1[1 + tid] = fmaf(sd, rs, b1[tid]);
    }
}

// ---------------- Linear1 (BN1 folded) + BN2 partial stats ----------------------
__global__ __launch_bounds__(256) void k_lin1(const float* __restrict__ W1) {
    extern __shared__ float smem[];
    float* hs = smem;              // 128 x 132
    float* ws = smem + 128 * 132;  // 50 x 132
    int tid = threadIdx.x;
    int row0 = blockIdx.x * 128;

    for (int idx = tid; idx < 128 * 32; idx += 256) {
        int r = idx >> 5, c4 = (idx & 31) << 2;
        *(float4*)(hs + r * 132 + c4) = *(const float4*)(g_H + (size_t)(row0 + r) * HID + c4);
    }
    for (int idx = tid; idx < 50 * 32; idx += 256) {
        int r = idx >> 5, c4 = (idx & 31) << 2;
        *(float4*)(ws + r * 132 + c4) = *(const float4*)(W1 + r * HID + c4);
    }
    __syncthreads();

    int rl = tid >> 1, half = tid & 1;
    float acc[25];
#pragma unroll
    for (int j = 0; j < 25; ++j) acc[j] = 0.0f;

    const float* hp  = hs + rl * 132;
    const float* wp0 = ws + (half * 25) * 132;
    for (int m4 = 0; m4 < 32; ++m4) {
        int mo = m4 * 4;
        float4 hv = *(const float4*)(hp + mo);
#pragma unroll
        for (int j = 0; j < 25; ++j) {
            float4 wv = *(const float4*)(wp0 + j * 132 + mo);
            dot4(acc[j], hv, wv);
        }
    }

    float alpha1 = g_s1[0];
    double lsum = 0.0, lsq = 0.0;
    int rowg = row0 + rl;
#pragma unroll
    for (int j = 0; j < 25; ++j) {
        float x = fmaf(alpha1, acc[j], g_s1[1 + half * 25 + j]);
        g_X[(size_t)rowg * 50 + half * 25 + j] = x;
        lsum += x;
        lsq  += (double)x * (double)x;
    }

    __shared__ double rsum[8], rsq[8];
#pragma unroll
    for (int o = 16; o; o >>= 1) {
        lsum += __shfl_down_sync(0xffffffffu, lsum, o);
        lsq  += __shfl_down_sync(0xffffffffu, lsq, o);
    }
    if ((tid & 31) == 0) { rsum[tid >> 5] = lsum; rsq[tid >> 5] = lsq; }
    __syncthreads();
    if (tid == 0) {
        double a = 0, b = 0;
        for (int w = 0; w < 8; ++w) { a += rsum[w]; b += rsq[w]; }
        g_part2[blockIdx.x * 2]     = a;
        g_part2[blockIdx.x * 2 + 1] = b;
    }
}

// ---------------- finalize BN2 --------------------------------------------------
__global__ void k_fin2(const float* __restrict__ gamma2, const float* __restrict__ beta2) {
    __shared__ double s0[256], s1b[256];
    int tid = threadIdx.x;
    double a = 0, b = 0;
    for (int i = tid; i < 3072; i += 256) { a += g_part2[i * 2]; b += g_part2[i * 2 + 1]; }
    s0[tid] = a; s1b[tid] = b;
    __syncthreads();
    for (int o = 128; o; o >>= 1) {
        if (tid < o) { s0[tid] += s0[tid + o]; s1b[tid] += s1b[tid + o]; }
        __syncthreads();
    }
    if (tid == 0) {
        double N = (double)BATCH * PRE * 50;
        double m = s0[0] / N;
        double v = s1b[0] / N - m * m;
        double al = (double)gamma2[0] / sqrt(v + 1e-5);
        g_s2[0] = (float)al;
        g_s2[1] = (float)((double)beta2[0] - al * m);
    }
}

// ---------------- ReLU(BN2(x)) stats for BN3 ------------------------------------
__global__ void k_relu_stats() {
    float al = g_s2[0], cc = g_s2[1];
    double ls = 0.0, lq = 0.0;
    size_t total = (size_t)BATCH * PRE * 50;
    for (size_t i = (size_t)blockIdx.x * blockDim.x + threadIdx.x; i < total;
         i += (size_t)gridDim.x * blockDim.x) {
        float r = fmaxf(fmaf(al, g_X[i], cc), 0.0f);
        ls += r;
        lq += (double)r * (double)r;
    }
    __shared__ double rsum[8], rsq[8];
    int tid = threadIdx.x;
#pragma unroll
    for (int o = 16; o; o >>= 1) {
        ls += __shfl_down_sync(0xffffffffu, ls, o);
        lq += __shfl_down_sync(0xffffffffu, lq, o);
    }
    if ((tid & 31) == 0) { rsum[tid >> 5] = ls; rsq[tid >> 5] = lq; }
    __syncthreads();
    if (tid == 0) {
        double a = 0, b = 0;
        for (int w = 0; w < 8; ++w) { a += rsum[w]; b += rsq[w]; }
        g_part3[blockIdx.x * 2]     = a;
        g_part3[blockIdx.x * 2 + 1] = b;
    }
}

// ---------------- finalize BN3, fold into Linear2 -------------------------------
__global__ void k_fin3(const float* __restrict__ gamma3, const float* __restrict__ beta3,
                       const float* __restrict__ W2, const float* __restrict__ b2) {
    __shared__ double s0[256], s1b[256];
    __shared__ float sa, sd;
    int tid = threadIdx.x;
    double a = 0, b = 0;
    for (int i = tid; i < 1024; i += 256) { a += g_part3[i * 2]; b += g_part3[i * 2 + 1]; }
    s0[tid] = a; s1b[tid] = b;
    __syncthreads();
    for (int o = 128; o; o >>= 1) {
        if (tid < o) { s0[tid] += s0[tid + o]; s1b[tid] += s1b[tid + o]; }
        __syncthreads();
    }
    if (tid == 0) {
        double N = (double)BATCH * PRE * 50;
        double m = s0[0] / N;
        double v = s1b[0] / N - m * m;
        double al = (double)gamma3[0] / sqrt(v + 1e-5);
        sa = (float)al;
        sd = (float)((double)beta3[0] - al * m);
    }
    __syncthreads();
    if (tid < 100) g_s3[tid] = sa * W2[tid];
    if (tid < 2) {
        float rs = 0.0f;
        for (int k = 0; k < 50; ++k) rs += W2[tid * 50 + k];
        g_s3[100 + tid] = fmaf(sd, rs, b2[tid]);
    }
}

// ---------------- final: ReLU(BN2(x)) @ (alpha3*W2)^T + b2_eff ------------------
__global__ void k_out(float* __restrict__ out) {
    int row = blockIdx.x * blockDim.x + threadIdx.x;  // 0 .. B*PRE-1 == b*12+t
    float al = g_s2[0], cc = g_s2[1];
    float a0 = 0.0f, a1 = 0.0f;
    const float* xp = g_X + (size_t)row * 50;
#pragma unroll
    for (int k = 0; k < 50; ++k) {
        float r = fmaxf(fmaf(al, xp[k], cc), 0.0f);
        a0 = fmaf(r, g_s3[k], a0);
        a1 = fmaf(r, g_s3[50 + k], a1);
    }
    out[row * 2]     = a0 + g_s3[100];
    out[row * 2 + 1] = a1 + g_s3[101];
}

// ---------------- host launcher -------------------------------------------------
extern "C" void kernel_launch(void* const* d_in, const int* in_sizes, int n_in,
                              void* d_out, int out_size) {
    const float* h   = (const float*)d_in[0];
    const float* c   = (const float*)d_in[1];
    const float* Wih = (const float*)d_in[2];
    const float* Whh = (const float*)d_in[3];
    const float* bih = (const float*)d_in[4];
    const float* bhh = (const float*)d_in[5];
    const float* g1  = (const float*)d_in[6];
    const float* be1 = (const float*)d_in[7];
    const float* g2  = (const float*)d_in[8];
    const float* be2 = (const float*)d_in[9];
    const float* g3  = (const float*)d_in[10];
    const float* be3 = (const float*)d_in[11];
    const float* W1  = (const float*)d_in[12];
    const float* b1  = (const float*)d_in[13];
    const float* W2  = (const float*)d_in[14];
    const float* b2  = (const float*)d_in[15];

    cudaFuncSetAttribute(k_step, cudaFuncAttributeMaxDynamicSharedMemorySize, 101376);
    cudaFuncSetAttribute(k_lin1, cudaFuncAttributeMaxDynamicSharedMemorySize, 93984);

    k_prep<<<256, 256>>>(Wih, Whh, bih, bhh);
    for (int t = 0; t < PRE; ++t)
        k_step<<<BATCH / 64, 256, 101376>>>(t, h, c);
    k_fin1<<<1, 256>>>(g1, be1, W1, b1);
    k_lin1<<<(BATCH * PRE) / 128, 256, 93984>>>(W1);
    k_fin2<<<1, 256>>>(g2, be2);
    k_relu_stats<<<1024, 256>>>();
    k_fin3<<<1, 256>>>(g3, be3, W2, b2);
    k_out<<<(BATCH * PRE) / 256, 256>>>((float*)d_out);
}

// round 3
// speedup vs baseline: 1.2234x; 1.2234x over previous
#include <cuda_runtime.h>

#define BATCH 32768
#define HID   128
#define PRE   12

// ---------------- device scratch ------------------------------------------------
__device__ float  g_W[4 * HID * HID];                 // combined W_ih + W_hh  [512][128]
__device__ float  g_bz[4 * HID];                      // combined bias
__device__ float  g_H[(size_t)BATCH * PRE * HID];     // hidden states, layout (B, PRE, HID)
__device__ float  g_c[(size_t)BATCH * HID];           // cell state (in-place per step)
__device__ float  g_X[(size_t)BATCH * PRE * 50];      // Linear1 output, layout (B*PRE, 50)
__device__ double g_part1[512 * 2];                   // BN1 partials (accumulated over 12 steps)
__device__ double g_part2[3072 * 2];                  // BN2 partials
__device__ double g_part3[1024 * 2];                  // BN3 partials
__device__ float  g_s1[64];                           // [0]=alpha1, [1..50]=bias_eff1
__device__ float  g_s2[4];                            // [0]=alpha2, [1]=beta2-alpha2*m2
__device__ float  g_s3[104];                          // [0..99]=alpha3*W2, [100..101]=b2_eff

__device__ __forceinline__ float sigf(float x) {
    return 1.0f / (1.0f + __expf(-x));
}
__device__ __forceinline__ float tanhfast(float x) {
    return fmaf(2.0f, 1.0f / (1.0f + __expf(-2.0f * x)), -1.0f);
}
__device__ __forceinline__ void dot4(float& a, const float4& u, const float4& v) {
    a = fmaf(u.x, v.x, fmaf(u.y, v.y, fmaf(u.z, v.z, fmaf(u.w, v.w, a))));
}

// ---------------- prep: combine weights/biases, zero BN1 partials ---------------
__global__ void k_prep(const float* __restrict__ Wih, const float* __restrict__ Whh,
                       const float* __restrict__ bih, const float* __restrict__ bhh) {
    int i = blockIdx.x * blockDim.x + threadIdx.x;
    for (int idx = i; idx < 4 * HID * HID; idx += gridDim.x * blockDim.x)
        g_W[idx] = Wih[idx] + Whh[idx];
    if (i < 4 * HID) g_bz[i] = bih[i] + bhh[i];
    if (i < 1024)    g_part1[i] = 0.0;
}

// ---------------- one LSTM step -------------------------------------------------
// Block: 256 threads, 64 batch rows. W streamed via SMEM in 4 chunks of 32 k-cols
// (all 4 gate rows per k). Thread tile: 4 rows x 4 gates x 2 k, where the two k
// are (kq, kq+16) so inner W loads stride exactly ONE 132-float row ->
// 33 16B-lines -> conflict-free across the quarter-warp (33 mod 8 == 1).
__global__ __launch_bounds__(256) void k_step(int t, const float* __restrict__ h0_in,
                                              const float* __restrict__ c0_in) {
    extern __shared__ float smem[];
    float* h_s = smem;             // 64 x 132 (padded)
    float* Wb  = smem + 64 * 132;  // 128 x 132 (4 gates x 32 k-rows)

    const int tid = threadIdx.x;
    const int rq  = tid >> 4;      // 0..15 -> 4 rows each
    const int kq  = tid & 15;      // 0..15 -> k outputs kq and kq+16
    const int r0  = blockIdx.x * 64;

    const float* hsrc;
    int hstride;
    if (t == 0) { hsrc = h0_in + (size_t)r0 * HID;                 hstride = HID; }
    else        { hsrc = g_H + ((size_t)r0 * PRE + (t - 1)) * HID; hstride = PRE * HID; }

    for (int idx = tid; idx < 64 * 32; idx += 256) {
        int row = idx >> 5, c4 = (idx & 31) << 2;
        float4 v = *(const float4*)(hsrc + (size_t)row * hstride + c4);
        *(float4*)(h_s + row * 132 + c4) = v;
    }

    const float* csrc = (t == 0) ? (c0_in + (size_t)r0 * HID) : (g_c + (size_t)r0 * HID);
    float*       cdst = g_c + (size_t)r0 * HID;

    double lsum = 0.0, lsq = 0.0;

    for (int kc = 0; kc < 4; ++kc) {
        __syncthreads();  // protect Wb from previous chunk's readers / h_s load
        for (int idx = tid; idx < 128 * 32; idx += 256) {
            int row = idx >> 5, c4 = (idx & 31) << 2;
            int g = row >> 5, kk = row & 31;
            float4 v = *(const float4*)(g_W + (g * HID + kc * 32 + kk) * HID + c4);
            *(float4*)(Wb + row * 132 + c4) = v;
        }
        __syncthreads();

        const int k0 = kc * 32 + kq;        // global k for lane's first output
        const int k1 = k0 + 16;             // second output
        float acc[4][4][2];
#pragma unroll
        for (int g = 0; g < 4; ++g) {
            float b0 = g_bz[g * HID + k0];
            float b1 = g_bz[g * HID + k1];
#pragma unroll
            for (int i = 0; i < 4; ++i) { acc[g][i][0] = b0; acc[g][i][1] = b1; }
        }

        const float* hrow = h_s + (rq * 4) * 132;
        const float* wrow = Wb + kq * 132;  // row stride 1 between adjacent lanes
#pragma unroll 4
        for (int m4 = 0; m4 < 32; ++m4) {
            const int mo = m4 * 4;
            float4 hv[4];
#pragma unroll
            for (int i = 0; i < 4; ++i)
                hv[i] = *(const float4*)(hrow + i * 132 + mo);
#pragma unroll
            for (int g = 0; g < 4; ++g) {
                const float* wp = wrow + g * 32 * 132 + mo;
                float4 w0 = *(const float4*)(wp);            // row kq
                float4 w1 = *(const float4*)(wp + 16 * 132); // row kq+16
#pragma unroll
                for (int i = 0; i < 4; ++i) {
                    dot4(acc[g][i][0], hv[i], w0);
                    dot4(acc[g][i][1], hv[i], w1);
                }
            }
        }

        // elementwise gate update for this k-chunk (fp32 stat accum, promoted once)
        float fsum = 0.0f, fsq = 0.0f;
#pragma unroll
        for (int i = 0; i < 4; ++i) {
            int lrow = rq * 4 + i;
            int b    = r0 + lrow;
            const float* cp = csrc + (size_t)lrow * HID;
            float*       cq = cdst + (size_t)lrow * HID;
            float*       hq = g_H + ((size_t)b * PRE + t) * HID;
#pragma unroll
            for (int kk = 0; kk < 2; ++kk) {
                int kg = kk ? k1 : k0;
                float zi = acc[0][i][kk], zf = acc[1][i][kk];
                float zg = acc[2][i][kk], zo = acc[3][i][kk];
                float ig = sigf(zi), fg = sigf(zf), gg = tanhfast(zg), og = sigf(zo);
                float c2 = fmaf(fg, cp[kg], ig * gg);
                float h2 = og * tanhfast(c2);
                cq[kg] = c2;
                hq[kg] = h2;
                fsum += h2;
                fsq   = fmaf(h2, h2, fsq);
            }
        }
        lsum += (double)fsum;
        lsq  += (double)fsq;
    }

    // deterministic block reduction, then single-writer accumulate
    __shared__ double rsum[8], rsq[8];
#pragma unroll
    for (int o = 16; o; o >>= 1) {
        lsum += __shfl_down_sync(0xffffffffu, lsum, o);
        lsq  += __shfl_down_sync(0xffffffffu, lsq, o);
    }
    if ((tid & 31) == 0) { rsum[tid >> 5] = lsum; rsq[tid >> 5] = lsq; }
    __syncthreads();
    if (tid == 0) {
        double a = 0, b = 0;
        for (int w = 0; w < 8; ++w) { a += rsum[w]; b += rsq[w]; }
        g_part1[blockIdx.x * 2]     += a;   // sole writer, sequential launches -> deterministic
        g_part1[blockIdx.x * 2 + 1] += b;
    }
}

// ---------------- finalize BN1, fold into Linear1 bias --------------------------
__global__ void k_fin1(const float* __restrict__ gamma1, const float* __restrict__ beta1,
                       const float* __restrict__ W1, const float* __restrict__ b1) {
    __shared__ double s0[256], s1b[256];
    __shared__ float sa, sd;
    int tid = threadIdx.x;
    s0[tid]  = g_part1[tid * 2]     + g_part1[(tid + 256) * 2];
    s1b[tid] = g_part1[tid * 2 + 1] + g_part1[(tid + 256) * 2 + 1];
    __syncthreads();
    for (int o = 128; o; o >>= 1) {
        if (tid < o) { s0[tid] += s0[tid + o]; s1b[tid] += s1b[tid + o]; }
        __syncthreads();
    }
    if (tid == 0) {
        double N = (double)BATCH * PRE * HID;
        double m = s0[0] / N;
        double v = s1b[0] / N - m * m;
        double a = (double)gamma1[0] / sqrt(v + 1e-5);
        sa = (float)a;
        sd = (float)((double)beta1[0] - a * m);
        g_s1[0] = sa;
    }
    __syncthreads();
    if (tid < 50) {
        float rs = 0.0f;
        for (int k = 0; k < HID; ++k) rs += W1[tid * HID + k];
        g_s1[1 + tid] = fmaf(sd, rs, b1[tid]);
    }
}

// ---------------- Linear1 (BN1 folded) + BN2 partial stats ----------------------
__global__ __launch_bounds__(256) void k_lin1(const float* __restrict__ W1) {
    extern __shared__ float smem[];
    float* hs = smem;              // 128 x 132
    float* ws = smem + 128 * 132;  // 50 x 132
    int tid = threadIdx.x;
    int row0 = blockIdx.x * 128;

    for (int idx = tid; idx < 128 * 32; idx += 256) {
        int r = idx >> 5, c4 = (idx & 31) << 2;
        *(float4*)(hs + r * 132 + c4) = *(const float4*)(g_H + (size_t)(row0 + r) * HID + c4);
    }
    for (int idx = tid; idx < 50 * 32; idx += 256) {
        int r = idx >> 5, c4 = (idx & 31) << 2;
        *(float4*)(ws + r * 132 + c4) = *(const float4*)(W1 + r * HID + c4);
    }
    __syncthreads();

    int rl = tid >> 1, half = tid & 1;
    float acc[25];
#pragma unroll
    for (int j = 0; j < 25; ++j) acc[j] = 0.0f;

    const float* hp  = hs + rl * 132;
    const float* wp0 = ws + (half * 25) * 132;
    for (int m4 = 0; m4 < 32; ++m4) {
        int mo = m4 * 4;
        float4 hv = *(const float4*)(hp + mo);
#pragma unroll
        for (int j = 0; j < 25; ++j) {
            float4 wv = *(const float4*)(wp0 + j * 132 + mo);
            dot4(acc[j], hv, wv);
        }
    }

    float alpha1 = g_s1[0];
    float fsum = 0.0f, fsq = 0.0f;
    int rowg = row0 + rl;
#pragma unroll
    for (int j = 0; j < 25; ++j) {
        float x = fmaf(alpha1, acc[j], g_s1[1 + half * 25 + j]);
        g_X[(size_t)rowg * 50 + half * 25 + j] = x;
        fsum += x;
        fsq   = fmaf(x, x, fsq);
    }
    double lsum = (double)fsum, lsq = (double)fsq;

    __shared__ double rsum[8], rsq[8];
#pragma unroll
    for (int o = 16; o; o >>= 1) {
        lsum += __shfl_down_sync(0xffffffffu, lsum, o);
        lsq  += __shfl_down_sync(0xffffffffu, lsq, o);
    }
    if ((tid & 31) == 0) { rsum[tid >> 5] = lsum; rsq[tid >> 5] = lsq; }
    __syncthreads();
    if (tid == 0) {
        double a = 0, b = 0;
        for (int w = 0; w < 8; ++w) { a += rsum[w]; b += rsq[w]; }
        g_part2[blockIdx.x * 2]     = a;
        g_part2[blockIdx.x * 2 + 1] = b;
    }
}

// ---------------- finalize BN2 --------------------------------------------------
__global__ void k_fin2(const float* __restrict__ gamma2, const float* __restrict__ beta2) {
    __shared__ double s0[256], s1b[256];
    int tid = threadIdx.x;
    double a = 0, b = 0;
    for (int i = tid; i < 3072; i += 256) { a += g_part2[i * 2]; b += g_part2[i * 2 + 1]; }
    s0[tid] = a; s1b[tid] = b;
    __syncthreads();
    for (int o = 128; o; o >>= 1) {
        if (tid < o) { s0[tid] += s0[tid + o]; s1b[tid] += s1b[tid + o]; }
        __syncthreads();
    }
    if (tid == 0) {
        double N = (double)BATCH * PRE * 50;
        double m = s0[0] / N;
        double v = s1b[0] / N - m * m;
        double al = (double)gamma2[0] / sqrt(v + 1e-5);
        g_s2[0] = (float)al;
        g_s2[1] = (float)((double)beta2[0] - al * m);
    }
}

// ---------------- ReLU(BN2(x)) stats for BN3 ------------------------------------
__global__ void k_relu_stats() {
    float al = g_s2[0], cc = g_s2[1];
    double ls = 0.0, lq = 0.0;
    size_t total = (size_t)BATCH * PRE * 50;
    for (size_t i = (size_t)blockIdx.x * blockDim.x + threadIdx.x; i < total;
         i += (size_t)gridDim.x * blockDim.x) {
        float r = fmaxf(fmaf(al, g_X[i], cc), 0.0f);
        ls += r;
        lq += (double)r * (double)r;
    }
    __shared__ double rsum[8], rsq[8];
    int tid = threadIdx.x;
#pragma unroll
    for (int o = 16; o; o >>= 1) {
        ls += __shfl_down_sync(0xffffffffu, ls, o);
        lq += __shfl_down_sync(0xffffffffu, lq, o);
    }
    if ((tid & 31) == 0) { rsum[tid >> 5] = ls; rsq[tid >> 5] = lq; }
    __syncthreads();
    if (tid == 0) {
        double a = 0, b = 0;
        for (int w = 0; w < 8; ++w) { a += rsum[w]; b += rsq[w]; }
        g_part3[blockIdx.x * 2]     = a;
        g_part3[blockIdx.x * 2 + 1] = b;
    }
}

// ---------------- finalize BN3, fold into Linear2 -------------------------------
__global__ void k_fin3(const float* __restrict__ gamma3, const float* __restrict__ beta3,
                       const float* __restrict__ W2, const float* __restrict__ b2) {
    __shared__ double s0[256], s1b[256];
    __shared__ float sa, sd;
    int tid = threadIdx.x;
    double a = 0, b = 0;
    for (int i = tid; i < 1024; i += 256) { a += g_part3[i * 2]; b += g_part3[i * 2 + 1]; }
    s0[tid] = a; s1b[tid] = b;
    __syncthreads();
    for (int o = 128; o; o >>= 1) {
        if (tid < o) { s0[tid] += s0[tid + o]; s1b[tid] += s1b[tid + o]; }
        __syncthreads();
    }
    if (tid == 0) {
        double N = (double)BATCH * PRE * 50;
        double m = s0[0] / N;
        double v = s1b[0] / N - m * m;
        double al = (double)gamma3[0] / sqrt(v + 1e-5);
        sa = (float)al;
        sd = (float)((double)beta3[0] - al * m);
    }
    __syncthreads();
    if (tid < 100) g_s3[tid] = sa * W2[tid];
    if (tid < 2) {
        float rs = 0.0f;
        for (int k = 0; k < 50; ++k) rs += W2[tid * 50 + k];
        g_s3[100 + tid] = fmaf(sd, rs, b2[tid]);
    }
}

// ---------------- final: ReLU(BN2(x)) @ (alpha3*W2)^T + b2_eff ------------------
__global__ void k_out(float* __restrict__ out) {
    int row = blockIdx.x * blockDim.x + threadIdx.x;  // 0 .. B*PRE-1 == b*12+t
    float al = g_s2[0], cc = g_s2[1];
    float a0 = 0.0f, a1 = 0.0f;
    const float* xp = g_X + (size_t)row * 50;
#pragma unroll
    for (int k = 0; k < 50; ++k) {
        float r = fmaxf(fmaf(al, xp[k], cc), 0.0f);
        a0 = fmaf(r, g_s3[k], a0);
        a1 = fmaf(r, g_s3[50 + k], a1);
    }
    out[row * 2]     = a0 + g_s3[100];
    out[row * 2 + 1] = a1 + g_s3[101];
}

// ---------------- host launcher -------------------------------------------------
extern "C" void kernel_launch(void* const* d_in, const int* in_sizes, int n_in,
                              void* d_out, int out_size) {
    const float* h   = (const float*)d_in[0];
    const float* c   = (const float*)d_in[1];
    const float* Wih = (const float*)d_in[2];
    const float* Whh = (const float*)d_in[3];
    const float* bih = (const float*)d_in[4];
    const float* bhh = (const float*)d_in[5];
    const float* g1  = (const float*)d_in[6];
    const float* be1 = (const float*)d_in[7];
    const float* g2  = (const float*)d_in[8];
    const float* be2 = (const float*)d_in[9];
    const float* g3  = (const float*)d_in[10];
    const float* be3 = (const float*)d_in[11];
    const float* W1  = (const float*)d_in[12];
    const float* b1  = (const float*)d_in[13];
    const float* W2  = (const float*)d_in[14];
    const float* b2  = (const float*)d_in[15];

    cudaFuncSetAttribute(k_step, cudaFuncAttributeMaxDynamicSharedMemorySize, 101376);
    cudaFuncSetAttribute(k_lin1, cudaFuncAttributeMaxDynamicSharedMemorySize, 93984);

    k_prep<<<256, 256>>>(Wih, Whh, bih, bhh);
    for (int t = 0; t < PRE; ++t)
        k_step<<<BATCH / 64, 256, 101376>>>(t, h, c);
    k_fin1<<<1, 256>>>(g1, be1, W1, b1);
    k_lin1<<<(BATCH * PRE) / 128, 256, 93984>>>(W1);
    k_fin2<<<1, 256>>>(g2, be2);
    k_relu_stats<<<1024, 256>>>();
    k_fin3<<<1, 256>>>(g3, be3, W2, b2);
    k_out<<<(BATCH * PRE) / 256, 256>>>((float*)d_out);
}